// round 4
// baseline (speedup 1.0000x reference)
#include <cuda_runtime.h>
#include <cuda_bf16.h>

// ZBL basis: per-edge screened Coulomb repulsion with polynomial cutoff,
// scatter-summed into receiver nodes.
//
// Inputs (metadata order):
//   d_in[0]: x               float32 [E, 1]   (E = 3,200,000)
//   d_in[1]: node_attrs      float32 [N, 10]  (N = 100,000)
//   d_in[2]: edge_index      int32   [2, E]
//   d_in[3]: atomic_numbers  int32   [10]
//   d_in[4]: covalent_radii  float32 [119]
// Output: V_ZBL float32 [N]
//
// Per-node element index (u8) staged in smem; per-pair physics in three
// 100-entry scalar SoA LUTs. Hot loop is fully branch-free: all math runs
// unconditionally, only the red.global.add.f32 is predicated (inline PTX,
// no BSSY/BSYNC divergence machinery).

#define MAX_NODES 100352   // >= N, multiple of 4 for word copies
#define N_ELEMS   10
#define NPAIR     (N_ELEMS * N_ELEMS)

__device__ unsigned char g_e[MAX_NODES];   // per-node element index 0..9

__device__ __forceinline__ float ex2f(float a) {
    float r; asm("ex2.approx.f32 %0, %1;" : "=f"(r) : "f"(a)); return r;
}
__device__ __forceinline__ float frcpf(float a) {
    float r; asm("rcp.approx.f32 %0, %1;" : "=f"(r) : "f"(a)); return r;
}

// Predicated no-return global float add: @p red.global.add.f32 — no branch.
__device__ __forceinline__ void red_add_if(float* addr, float val, float rr) {
    asm volatile(
        "{\n\t"
        ".reg .pred p;\n\t"
        "setp.lt.f32 p, %1, 0f3F800000;\n\t"   // rr < 1.0f
        "@p red.global.add.f32 [%0], %2;\n\t"
        "}"
        :: "l"(addr), "f"(rr), "f"(val)
        : "memory");
}

// ---------------------------------------------------------------------------
// Node prep: argmax over 10 attrs -> element index (u8); zero the output.
// ---------------------------------------------------------------------------
__global__ void node_prep_kernel(const float* __restrict__ attrs,
                                 float* __restrict__ out,
                                 int n_nodes, int out_n) {
    __shared__ float s[256 * N_ELEMS];
    int base = blockIdx.x * 256;
    int nloc = n_nodes - base;
    if (nloc > 256) nloc = 256;
    if (nloc > 0) {
        int total = nloc * N_ELEMS;                       // <= 2560 floats
        const float* src = attrs + (size_t)base * N_ELEMS; // 16B-aligned
        int nv4 = total >> 2;
        const float4* s4 = (const float4*)src;
        float4* d4 = (float4*)s;
        for (int k = threadIdx.x; k < nv4; k += 256) d4[k] = s4[k];
        for (int k = (nv4 << 2) + threadIdx.x; k < total; k += 256)
            s[k] = src[k];
    }
    __syncthreads();

    int i = base + threadIdx.x;
    if ((int)threadIdx.x < nloc) {
        const float* a = s + threadIdx.x * N_ELEMS;
        int best = 0;
        float bv = a[0];
#pragma unroll
        for (int j = 1; j < N_ELEMS; j++) {
            float v = a[j];
            if (v > bv) { bv = v; best = j; }
        }
        g_e[i] = (unsigned char)best;
    }
    if (i < out_n) out[i] = 0.0f;
}

// ---------------------------------------------------------------------------
// Edge kernel
// ---------------------------------------------------------------------------
__device__ __forceinline__ void process_edge(
    int s, int r, float xi,
    const unsigned char* __restrict__ s_e,
    const float* __restrict__ s_irm,
    const float* __restrict__ s_ia,
    const float* __restrict__ s_pf,
    float* __restrict__ out)
{
    int eu = s_e[s];
    int ev = s_e[r];
    int idx = eu * N_ELEMS + ev;
    float inv_rmax = s_irm[idx];
    float invA     = s_ia[idx];
    float pref     = s_pf[idx];

    float rr = xi * inv_rmax;
    float t  = xi * invA;

    // exp(-c*t) as ex2((-c*log2e)*t); constants folded at compile time
    const float K0 = -3.2f    * 1.44269504f;
    const float K1 = -0.9423f * 1.44269504f;
    const float K2 = -0.4028f * 1.44269504f;
    const float K3 = -0.2016f * 1.44269504f;
    float phi = 0.1818f  * ex2f(K0 * t)
              + 0.5099f  * ex2f(K1 * t)
              + 0.2802f  * ex2f(K2 * t)
              + 0.02817f * ex2f(K3 * t);

    // polynomial envelope, p=6: 1 - 28 r^6 + 48 r^7 - 21 r^8
    float r2 = rr * rr;
    float r3 = r2 * rr;
    float r6 = r3 * r3;
    float env = fmaf(-28.0f, r6, 1.0f);
    env = fmaf(48.0f, r6 * rr, env);
    env = fmaf(-21.0f, r6 * r2, env);

    float val = pref * phi * frcpf(xi) * env;
    red_add_if(out + r, val, rr);
}

__global__ void edge_kernel(const float* __restrict__ x,
                            const int* __restrict__ ei,
                            const int* __restrict__ atomic_numbers,
                            const float* __restrict__ radii_g,
                            float* __restrict__ out,
                            int n_edges, int n_nodes) {
    extern __shared__ char smem[];
    float* s_irm = (float*)smem;           // NPAIR
    float* s_ia  = s_irm + NPAIR;          // NPAIR
    float* s_pf  = s_ia + NPAIR;           // NPAIR
    unsigned char* s_e = (unsigned char*)(s_pf + NPAIR);

    int tid = threadIdx.x;
    int nt = blockDim.x;

    // Build SoA pair LUTs
    if (tid < NPAIR) {
        int i = tid / N_ELEMS, j = tid % N_ELEMS;
        int Zi = atomic_numbers[i], Zj = atomic_numbers[j];
        float Zif = (float)Zi, Zjf = (float)Zj;
        s_irm[tid] = 1.0f / (radii_g[Zi] + radii_g[Zj]);
        s_ia[tid]  = (powf(Zif, 0.3f) + powf(Zjf, 0.3f))
                     * (1.0f / (0.4543f * 0.529f));
        s_pf[tid]  = 0.5f * 14.3996f * Zif * Zjf;
    }
    // Copy element-index table into smem (word-wide, coalesced, L2-resident)
    {
        const unsigned int* ge32 = (const unsigned int*)g_e;
        unsigned int* se32 = (unsigned int*)s_e;
        int nwords = (n_nodes + 3) >> 2;
        for (int w = tid; w < nwords; w += nt) se32[w] = ge32[w];
    }
    __syncthreads();

    const int4*   si = (const int4*)ei;
    const int4*   ri = (const int4*)(ei + n_edges);
    const float4* x4 = (const float4*)x;
    int n4 = n_edges >> 2;
    int gstride = gridDim.x * nt;

    for (int g = blockIdx.x * nt + tid; g < n4; g += gstride) {
        int4 ss = si[g];
        int4 rr = ri[g];
        float4 xx = x4[g];
        process_edge(ss.x, rr.x, xx.x, s_e, s_irm, s_ia, s_pf, out);
        process_edge(ss.y, rr.y, xx.y, s_e, s_irm, s_ia, s_pf, out);
        process_edge(ss.z, rr.z, xx.z, s_e, s_irm, s_ia, s_pf, out);
        process_edge(ss.w, rr.w, xx.w, s_e, s_irm, s_ia, s_pf, out);
    }
    // scalar tail
    for (int i = (n4 << 2) + blockIdx.x * nt + tid; i < n_edges; i += gstride) {
        process_edge(ei[i], ei[n_edges + i], x[i], s_e, s_irm, s_ia, s_pf, out);
    }
}

extern "C" void kernel_launch(void* const* d_in, const int* in_sizes, int n_in,
                              void* d_out, int out_size) {
    const float* x              = (const float*)d_in[0];
    const float* node_attrs     = (const float*)d_in[1];
    const int*   edge_index     = (const int*)  d_in[2];
    const int*   atomic_numbers = (const int*)  d_in[3];
    const float* covalent_radii = (const float*)d_in[4];
    float* out = (float*)d_out;

    int n_edges = in_sizes[0];            // E
    int n_nodes = in_sizes[1] / N_ELEMS;  // N

    {
        int cover = n_nodes > out_size ? n_nodes : out_size;
        int blocks = (cover + 255) / 256;
        node_prep_kernel<<<blocks, 256>>>(node_attrs, out, n_nodes, out_size);
    }

    int smem_bytes = 3 * NPAIR * (int)sizeof(float) + MAX_NODES;
    cudaFuncSetAttribute(edge_kernel,
                         cudaFuncAttributeMaxDynamicSharedMemorySize,
                         smem_bytes);
    edge_kernel<<<304, 1024, smem_bytes>>>(x, edge_index, atomic_numbers,
                                           covalent_radii, out,
                                           n_edges, n_nodes);
}

// round 5
// speedup vs baseline: 1.0992x; 1.0992x over previous
#include <cuda_runtime.h>
#include <cuda_bf16.h>

// ZBL basis: per-edge screened Coulomb repulsion with polynomial cutoff,
// scatter-summed into receiver nodes.
//
// Inputs (metadata order):
//   d_in[0]: x               float32 [E, 1]   (E = 3,200,000)
//   d_in[1]: node_attrs      float32 [N, 10]  (N = 100,000)
//   d_in[2]: edge_index      int32   [2, E]
//   d_in[3]: atomic_numbers  int32   [10]
//   d_in[4]: covalent_radii  float32 [119]
// Output: V_ZBL float32 [N]
//
// Per-node element index (u8) staged in smem; per-pair physics in three
// 100-entry scalar SoA LUTs. Hot loop branch-free; only the
// red.global.add.f32 is predicated.
//
// CRITICAL: smem/block = ~101KB -> exactly 2 resident blocks/SM. Grid MUST be
// 2*148=296 so the grid-stride split completes in ONE wave; 304 caused a
// nearly-full second wave on 8 SMs (~1.9x slowdown).

#define MAX_NODES 100352   // >= N, multiple of 4 for word copies
#define N_ELEMS   10
#define NPAIR     (N_ELEMS * N_ELEMS)
#define EDGE_GRID 296      // 2 blocks/SM x 148 SMs: one full wave

__device__ unsigned char g_e[MAX_NODES];   // per-node element index 0..9

__device__ __forceinline__ float ex2f(float a) {
    float r; asm("ex2.approx.f32 %0, %1;" : "=f"(r) : "f"(a)); return r;
}
__device__ __forceinline__ float frcpf(float a) {
    float r; asm("rcp.approx.f32 %0, %1;" : "=f"(r) : "f"(a)); return r;
}

// Predicated no-return global float add: @p red.global.add.f32 — no branch.
__device__ __forceinline__ void red_add_if(float* addr, float val, float rr) {
    asm volatile(
        "{\n\t"
        ".reg .pred p;\n\t"
        "setp.lt.f32 p, %1, 0f3F800000;\n\t"   // rr < 1.0f
        "@p red.global.add.f32 [%0], %2;\n\t"
        "}"
        :: "l"(addr), "f"(rr), "f"(val)
        : "memory");
}

// ---------------------------------------------------------------------------
// Node prep: argmax over 10 attrs -> element index (u8); zero the output.
// ---------------------------------------------------------------------------
__global__ void node_prep_kernel(const float* __restrict__ attrs,
                                 float* __restrict__ out,
                                 int n_nodes, int out_n) {
    __shared__ float s[256 * N_ELEMS];
    int base = blockIdx.x * 256;
    int nloc = n_nodes - base;
    if (nloc > 256) nloc = 256;
    if (nloc > 0) {
        int total = nloc * N_ELEMS;                        // <= 2560 floats
        const float* src = attrs + (size_t)base * N_ELEMS; // 16B-aligned
        int nv4 = total >> 2;
        const float4* s4 = (const float4*)src;
        float4* d4 = (float4*)s;
        for (int k = threadIdx.x; k < nv4; k += 256) d4[k] = s4[k];
        for (int k = (nv4 << 2) + threadIdx.x; k < total; k += 256)
            s[k] = src[k];
    }
    __syncthreads();

    int i = base + threadIdx.x;
    if ((int)threadIdx.x < nloc) {
        const float* a = s + threadIdx.x * N_ELEMS;
        int best = 0;
        float bv = a[0];
#pragma unroll
        for (int j = 1; j < N_ELEMS; j++) {
            float v = a[j];
            if (v > bv) { bv = v; best = j; }
        }
        g_e[i] = (unsigned char)best;
    }
    if (i < out_n) out[i] = 0.0f;
}

// ---------------------------------------------------------------------------
// Edge kernel
// ---------------------------------------------------------------------------
__device__ __forceinline__ void process_edge(
    int s, int r, float xi,
    const unsigned char* __restrict__ s_e,
    const float* __restrict__ s_irm,
    const float* __restrict__ s_ia,
    const float* __restrict__ s_pf,
    float* __restrict__ out)
{
    int eu = s_e[s];
    int ev = s_e[r];
    int idx = eu * N_ELEMS + ev;
    float inv_rmax = s_irm[idx];
    float invA     = s_ia[idx];
    float pref     = s_pf[idx];

    float rr = xi * inv_rmax;
    float t  = xi * invA;

    // exp(-c*t) as ex2((-c*log2e)*t); constants folded at compile time
    const float K0 = -3.2f    * 1.44269504f;
    const float K1 = -0.9423f * 1.44269504f;
    const float K2 = -0.4028f * 1.44269504f;
    const float K3 = -0.2016f * 1.44269504f;
    float phi = 0.1818f  * ex2f(K0 * t)
              + 0.5099f  * ex2f(K1 * t)
              + 0.2802f  * ex2f(K2 * t)
              + 0.02817f * ex2f(K3 * t);

    // polynomial envelope, p=6: 1 - 28 r^6 + 48 r^7 - 21 r^8
    float r2 = rr * rr;
    float r3 = r2 * rr;
    float r6 = r3 * r3;
    float env = fmaf(-28.0f, r6, 1.0f);
    env = fmaf(48.0f, r6 * rr, env);
    env = fmaf(-21.0f, r6 * r2, env);

    float val = pref * phi * frcpf(xi) * env;
    red_add_if(out + r, val, rr);
}

__global__ void edge_kernel(const float* __restrict__ x,
                            const int* __restrict__ ei,
                            const int* __restrict__ atomic_numbers,
                            const float* __restrict__ radii_g,
                            float* __restrict__ out,
                            int n_edges, int n_nodes) {
    extern __shared__ char smem[];
    float* s_irm = (float*)smem;           // NPAIR
    float* s_ia  = s_irm + NPAIR;          // NPAIR
    float* s_pf  = s_ia + NPAIR;           // NPAIR
    unsigned char* s_e = (unsigned char*)(s_pf + NPAIR);

    int tid = threadIdx.x;
    int nt = blockDim.x;

    // Build SoA pair LUTs
    if (tid < NPAIR) {
        int i = tid / N_ELEMS, j = tid % N_ELEMS;
        int Zi = atomic_numbers[i], Zj = atomic_numbers[j];
        float Zif = (float)Zi, Zjf = (float)Zj;
        s_irm[tid] = 1.0f / (radii_g[Zi] + radii_g[Zj]);
        s_ia[tid]  = (powf(Zif, 0.3f) + powf(Zjf, 0.3f))
                     * (1.0f / (0.4543f * 0.529f));
        s_pf[tid]  = 0.5f * 14.3996f * Zif * Zjf;
    }
    // Copy element-index table into smem (word-wide, coalesced, L2-resident)
    {
        const unsigned int* ge32 = (const unsigned int*)g_e;
        unsigned int* se32 = (unsigned int*)s_e;
        int nwords = (n_nodes + 3) >> 2;
        for (int w = tid; w < nwords; w += nt) se32[w] = ge32[w];
    }
    __syncthreads();

    const int4*   si = (const int4*)ei;
    const int4*   ri = (const int4*)(ei + n_edges);
    const float4* x4 = (const float4*)x;
    int n4 = n_edges >> 2;
    int gstride = gridDim.x * nt;

    for (int g = blockIdx.x * nt + tid; g < n4; g += gstride) {
        int4 ss = si[g];
        int4 rr = ri[g];
        float4 xx = x4[g];
        process_edge(ss.x, rr.x, xx.x, s_e, s_irm, s_ia, s_pf, out);
        process_edge(ss.y, rr.y, xx.y, s_e, s_irm, s_ia, s_pf, out);
        process_edge(ss.z, rr.z, xx.z, s_e, s_irm, s_ia, s_pf, out);
        process_edge(ss.w, rr.w, xx.w, s_e, s_irm, s_ia, s_pf, out);
    }
    // scalar tail
    for (int i = (n4 << 2) + blockIdx.x * nt + tid; i < n_edges; i += gstride) {
        process_edge(ei[i], ei[n_edges + i], x[i], s_e, s_irm, s_ia, s_pf, out);
    }
}

extern "C" void kernel_launch(void* const* d_in, const int* in_sizes, int n_in,
                              void* d_out, int out_size) {
    const float* x              = (const float*)d_in[0];
    const float* node_attrs     = (const float*)d_in[1];
    const int*   edge_index     = (const int*)  d_in[2];
    const int*   atomic_numbers = (const int*)  d_in[3];
    const float* covalent_radii = (const float*)d_in[4];
    float* out = (float*)d_out;

    int n_edges = in_sizes[0];            // E
    int n_nodes = in_sizes[1] / N_ELEMS;  // N

    {
        int cover = n_nodes > out_size ? n_nodes : out_size;
        int blocks = (cover + 255) / 256;
        node_prep_kernel<<<blocks, 256>>>(node_attrs, out, n_nodes, out_size);
    }

    int smem_bytes = 3 * NPAIR * (int)sizeof(float) + MAX_NODES;
    cudaFuncSetAttribute(edge_kernel,
                         cudaFuncAttributeMaxDynamicSharedMemorySize,
                         smem_bytes);
    // ONE full wave: 2 blocks/SM (smem-limited) x 148 SMs
    edge_kernel<<<EDGE_GRID, 1024, smem_bytes>>>(x, edge_index, atomic_numbers,
                                                 covalent_radii, out,
                                                 n_edges, n_nodes);
}